// round 12
// baseline (speedup 1.0000x reference)
#include <cuda_runtime.h>
#include <cuda_bf16.h>
#include <cstdint>

// Fixed shapes
#define Nb 8
#define Ld 4096
#define Sd 4096
#define Hh 8
#define Dd 64
#define Mm 64
#define CH 16           // split-K chunks over S
#define SC (Sd / CH)    // 256 s-rows per chunk
#define TS 4            // phase-2 L segments: 256 CTAs
#define EPSV 1e-6f
#define NH (Nb * Hh)
#define KVF_NH 5120     // 8 k8 * 32 slots * 20 floats (permuted KV per head)

// Scratch (allocation-free rule: __device__ globals)
__device__ float g_KVp[CH * NH * Dd * Mm];   // per-chunk partial KV (fp32)
__device__ float g_Ksp[CH * NH * Dd];        // per-chunk partial Ksum (fp32)
__device__ float g_KVf[NH * KVF_NH];         // reduced KV, tf32 bits, fragment-permuted
__device__ float g_Ksum[NH * Dd];            // reduced Ksum (fp32)

__device__ __forceinline__ float phi(float x) {
    return x > 0.f ? x + 1.f : __expf(x);    // elu(x)+1
}

__device__ __forceinline__ uint32_t to_tf32(float x) {
    uint32_t u;
    asm("cvt.rna.tf32.f32 %0, %1;" : "=r"(u) : "f"(x));
    return u;
}

__device__ __forceinline__ void mma_tf32(float* d,
                                         uint32_t a0, uint32_t a1, uint32_t a2, uint32_t a3,
                                         uint32_t b0, uint32_t b1) {
    asm volatile(
        "mma.sync.aligned.m16n8k8.row.col.f32.tf32.tf32.f32 "
        "{%0,%1,%2,%3}, {%4,%5,%6,%7}, {%8,%9}, {%0,%1,%2,%3};\n"
        : "+f"(d[0]), "+f"(d[1]), "+f"(d[2]), "+f"(d[3])
        : "r"(a0), "r"(a1), "r"(a2), "r"(a3), "r"(b0), "r"(b1));
}

__device__ __forceinline__ void cp16(uint32_t saddr, const void* gaddr) {
    asm volatile("cp.async.cg.shared.global [%0], [%1], 16;\n"
                 :: "r"(saddr), "l"(gaddr));
}

// ───────────────────────── Phase 1: per-chunk KV partials ─────────────────────────
// (proven ~35us version — unchanged)
__global__ __launch_bounds__(256) void la_kv_kernel(const float* __restrict__ kk,
                                                    const float* __restrict__ vv,
                                                    const float* __restrict__ mask) {
    const int c = blockIdx.x, h = blockIdx.y, n = blockIdx.z;
    const int nh = n * Hh + h;
    const int tid = threadIdx.x;
    const int warp = tid >> 5, lane = tid & 31;
    const int r = lane >> 2, q4 = lane & 3;
    const int d0 = (warp >> 1) * 16, m0 = (warp & 1) * 32;
    const int lrow = tid >> 4, lcol = tid & 15;

    __shared__ float Ks[32][72];
    __shared__ float Vs[32][72];
    __shared__ float ksum_s[64];

    if (tid < 64) ksum_s[tid] = 0.f;

    float acc[4][4] = {};
    float ks4[4] = {0.f, 0.f, 0.f, 0.f};

    const size_t s0 = (size_t)c * SC;
    const float* kbase = kk + (size_t)n * Sd * 512 + h * Dd;
    const float* vbase = vv + (size_t)n * Sd * 512 + h * Mm;
    const float* mbase = mask + (size_t)n * Sd;

    float4 kr[2], vr[2];
    float mr[2];

    #pragma unroll
    for (int p = 0; p < 2; p++) {
        size_t sg = s0 + p * 16 + lrow;
        kr[p] = *(const float4*)(kbase + sg * 512 + lcol * 4);
        vr[p] = *(const float4*)(vbase + sg * 512 + lcol * 4);
        mr[p] = __ldg(mbase + sg);
    }

    for (int it = 0; it < SC / 32; it++) {
        #pragma unroll
        for (int p = 0; p < 2; p++) {
            int row = p * 16 + lrow;
            float pk0 = phi(kr[p].x) * mr[p], pk1 = phi(kr[p].y) * mr[p];
            float pk2 = phi(kr[p].z) * mr[p], pk3 = phi(kr[p].w) * mr[p];
            ks4[0] += pk0; ks4[1] += pk1; ks4[2] += pk2; ks4[3] += pk3;
            uint4 ku; ku.x = to_tf32(pk0); ku.y = to_tf32(pk1);
                      ku.z = to_tf32(pk2); ku.w = to_tf32(pk3);
            uint4 vu; vu.x = to_tf32(vr[p].x); vu.y = to_tf32(vr[p].y);
                      vu.z = to_tf32(vr[p].z); vu.w = to_tf32(vr[p].w);
            *(uint4*)&Ks[row][lcol * 4] = ku;
            *(uint4*)&Vs[row][lcol * 4] = vu;
        }
        __syncthreads();

        if (it + 1 < SC / 32) {
            #pragma unroll
            for (int p = 0; p < 2; p++) {
                size_t sg = s0 + (it + 1) * 32 + p * 16 + lrow;
                kr[p] = *(const float4*)(kbase + sg * 512 + lcol * 4);
                vr[p] = *(const float4*)(vbase + sg * 512 + lcol * 4);
                mr[p] = __ldg(mbase + sg);
            }
        }

        #pragma unroll
        for (int k8 = 0; k8 < 4; k8++) {
            int sA = k8 * 8 + q4;
            uint32_t a0 = __float_as_uint(Ks[sA][d0 + r]);
            uint32_t a1 = __float_as_uint(Ks[sA][d0 + r + 8]);
            uint32_t a2 = __float_as_uint(Ks[sA + 4][d0 + r]);
            uint32_t a3 = __float_as_uint(Ks[sA + 4][d0 + r + 8]);
            #pragma unroll
            for (int j = 0; j < 4; j++) {
                uint32_t b0 = __float_as_uint(Vs[sA][m0 + 8 * j + r]);
                uint32_t b1 = __float_as_uint(Vs[sA + 4][m0 + 8 * j + r]);
                mma_tf32(acc[j], a0, a1, a2, a3, b0, b1);
            }
        }
        __syncthreads();
    }

    #pragma unroll
    for (int q = 0; q < 4; q++) atomicAdd(&ksum_s[lcol * 4 + q], ks4[q]);
    __syncthreads();
    if (tid < 64) g_Ksp[(c * NH + nh) * Dd + tid] = ksum_s[tid];

    float* kvp = g_KVp + ((size_t)c * NH + nh) * (Dd * Mm);
    #pragma unroll
    for (int j = 0; j < 4; j++) {
        int m = m0 + 8 * j + 2 * q4;
        *(float2*)&kvp[(d0 + r) * Mm + m]     = make_float2(acc[j][0], acc[j][1]);
        *(float2*)&kvp[(d0 + r + 8) * Mm + m] = make_float2(acc[j][2], acc[j][3]);
    }
}

// ──── Reduce: CH partials → fragment-permuted tf32 KV (g_KVf) + Ksum ────
// Permuted layout per nh: slot (k8, r, q4) at offset (k8*32 + r*4 + q4)*20,
// holding [b0 j=0..7][b1 j=0..7]; b0 row = 8k8+q4, b1 row = 8k8+q4+4, col = 8j+r.
#define KV4 (NH * Dd * Mm / 4)     // 65536 float4
#define KS4 (NH * Dd / 4)          // 1024 float4
__global__ __launch_bounds__(256) void la_red_kernel() {
    int i = blockIdx.x * 256 + threadIdx.x;
    if (i < KV4) {
        float4 s = make_float4(0.f, 0.f, 0.f, 0.f);
        #pragma unroll
        for (int c = 0; c < CH; c++) {
            float4 x = *(const float4*)(g_KVp + (size_t)c * (NH * Dd * Mm) + i * 4);
            s.x += x.x; s.y += x.y; s.z += x.z; s.w += x.w;
        }
        int nhq = i >> 10;               // 1024 float4 per nh
        int inner = i & 1023;
        int d = inner >> 4;
        int mb = (inner & 15) * 4;
        int k8 = d >> 3, dq = d & 7;
        int q4 = dq & 3, bsel = dq >> 2;
        float* dst = g_KVf + (size_t)nhq * KVF_NH;
        float vals[4] = {s.x, s.y, s.z, s.w};
        #pragma unroll
        for (int t = 0; t < 4; t++) {
            int m = mb + t;
            int r = m & 7, j = m >> 3;
            dst[(k8 * 32 + r * 4 + q4) * 20 + bsel * 8 + j] =
                __uint_as_float(to_tf32(vals[t]));
        }
    } else if (i < KV4 + KS4) {
        int i2 = i - KV4;
        float4 s = make_float4(0.f, 0.f, 0.f, 0.f);
        #pragma unroll
        for (int c = 0; c < CH; c++) {
            float4 x = *(const float4*)(g_Ksp + c * (NH * Dd) + i2 * 4);
            s.x += x.x; s.y += x.y; s.z += x.z; s.w += x.w;
        }
        *(float4*)(g_Ksum + i2 * 4) = s;
    }
}

// ───────────── Phase 2: warp-autonomous, LDS.128 B fragments, Z via 9th mma tile ──
// grid (TS, H, N) = 256 CTAs, 256 threads. Warp w: 16-row tiles t = it*8 + w.
#define QROWP 68                       // raw-Q smem row pitch (floats)
#define SLOT  (16 * QROWP)             // one ring stage (floats)
#define P2_SMEM ((KVF_NH + 8 * 2 * SLOT) * 4)

__global__ __launch_bounds__(256) void la_out_kernel(const float* __restrict__ qq,
                                                     float* __restrict__ out) {
    extern __shared__ float sm[];
    float* KVf = sm;                       // [KVF_NH] permuted tf32 fragments
    float* Qring = sm + KVF_NH;            // 8 warps x 2 stages x SLOT (raw fp32)

    const int seg = blockIdx.x, h = blockIdx.y, n = blockIdx.z;
    const int nh = n * Hh + h;
    const int tid = threadIdx.x;
    const int warp = tid >> 5, lane = tid & 31;
    const int r = lane >> 2, q4 = lane & 3;

    // cooperative KVf load (flat copy, already permuted+tf32)
    const float* kvb = g_KVf + (size_t)nh * KVF_NH;
    #pragma unroll
    for (int p = 0; p < 5; p++) {
        int idx4 = tid + p * 256;          // 0..1279
        *(float4*)&KVf[idx4 * 4] = *(const float4*)(kvb + idx4 * 4);
    }

    const size_t lbase = (size_t)n * Ld + (size_t)seg * (Ld / TS);
    const float* qseg = qq + lbase * 512 + h * Dd;
    float* oseg = out + lbase * 512 + h * Mm;

    float* myring = Qring + warp * 2 * SLOT;
    const uint32_t ring_s = (uint32_t)__cvta_generic_to_shared(myring);

    const int NT = (Ld / TS) / (8 * 16);   // 8 iterations per warp

    // prologue: issue tiles it=0,1 into stages 0,1
    #pragma unroll
    for (int pre = 0; pre < 2; pre++) {
        int trow = (pre * 8 + warp) * 16;
        uint32_t sbase = ring_s + pre * SLOT * 4;
        #pragma unroll
        for (int i = 0; i < 8; i++) {
            int chunk = lane + 32 * i;
            int row = chunk >> 4, c = chunk & 15;
            cp16(sbase + (row * QROWP + c * 4) * 4,
                 qseg + (size_t)(trow + row) * 512 + c * 4);
        }
        asm volatile("cp.async.commit_group;\n");
    }

    __syncthreads();   // KVf ready (single block barrier)

    // Ksum B-fragments for the denominator tile: tf32, r-independent
    uint32_t ksAu[8], ksBu[8];
    const float* ksb = g_Ksum + nh * Dd;
    #pragma unroll
    for (int k8 = 0; k8 < 8; k8++) {
        ksAu[k8] = to_tf32(__ldg(ksb + 8 * k8 + q4));
        ksBu[k8] = to_tf32(__ldg(ksb + 8 * k8 + q4 + 4));
    }

    // this lane's B-slot base within each k8 section (slot idx == lane)
    const int bslot = lane * 20;

    #pragma unroll 1
    for (int it = 0; it < NT; it++) {
        float* qs = myring + (it & 1) * SLOT;

        asm volatile("cp.async.wait_group 1;\n" ::: "memory");
        __syncwarp();

        // read raw A fragments
        float ar[8][4];
        #pragma unroll
        for (int k8 = 0; k8 < 8; k8++) {
            int dk = 8 * k8;
            ar[k8][0] = qs[r * QROWP + dk + q4];
            ar[k8][1] = qs[(r + 8) * QROWP + dk + q4];
            ar[k8][2] = qs[r * QROWP + dk + q4 + 4];
            ar[k8][3] = qs[(r + 8) * QROWP + dk + q4 + 4];
        }
        __syncwarp();

        // refill this stage with tile it+2 (always commit)
        if (it + 2 < NT) {
            int trow = ((it + 2) * 8 + warp) * 16;
            uint32_t sbase = ring_s + (it & 1) * SLOT * 4;
            #pragma unroll
            for (int i = 0; i < 8; i++) {
                int chunk = lane + 32 * i;
                int row = chunk >> 4, c = chunk & 15;
                cp16(sbase + (row * QROWP + c * 4) * 4,
                     qseg + (size_t)(trow + row) * 512 + c * 4);
            }
        }
        asm volatile("cp.async.commit_group;\n");

        // phi + tf32 convert (no scalar dot chain — Z comes from mma tile 9)
        uint32_t af[8][4];
        #pragma unroll
        for (int k8 = 0; k8 < 8; k8++) {
            af[k8][0] = to_tf32(phi(ar[k8][0]));
            af[k8][1] = to_tf32(phi(ar[k8][1]));
            af[k8][2] = to_tf32(phi(ar[k8][2]));
            af[k8][3] = to_tf32(phi(ar[k8][3]));
        }

        // mma: 8 output tiles + 1 denominator tile (B = Ksum broadcast)
        float acc[8][4] = {};
        float accz[4] = {};
        #pragma unroll
        for (int k8 = 0; k8 < 8; k8++) {
            const float* bp = &KVf[k8 * 640 + bslot];
            float4 b01 = *(const float4*)(bp);        // b0 j0..3
            float4 b02 = *(const float4*)(bp + 4);    // b0 j4..7
            float4 b11 = *(const float4*)(bp + 8);    // b1 j0..3
            float4 b12 = *(const float4*)(bp + 12);   // b1 j4..7
            const float b0a[8] = {b01.x, b01.y, b01.z, b01.w, b02.x, b02.y, b02.z, b02.w};
            const float b1a[8] = {b11.x, b11.y, b11.z, b11.w, b12.x, b12.y, b12.z, b12.w};
            #pragma unroll
            for (int j = 0; j < 8; j++)
                mma_tf32(acc[j], af[k8][0], af[k8][1], af[k8][2], af[k8][3],
                         __float_as_uint(b0a[j]), __float_as_uint(b1a[j]));
            mma_tf32(accz, af[k8][0], af[k8][1], af[k8][2], af[k8][3],
                     ksAu[k8], ksBu[k8]);
        }
        float z1 = 1.f / (accz[0] + EPSV);
        float z2 = 1.f / (accz[2] + EPSV);

        // store 16 x 64
        int trow = (it * 8 + warp) * 16;
        float* ob = oseg + (size_t)trow * 512;
        #pragma unroll
        for (int j = 0; j < 8; j++) {
            int m = 8 * j + 2 * q4;
            *(float2*)&ob[(size_t)r * 512 + m] =
                make_float2(acc[j][0] * z1, acc[j][1] * z1);
            *(float2*)&ob[(size_t)(r + 8) * 512 + m] =
                make_float2(acc[j][2] * z2, acc[j][3] * z2);
        }
    }
}

extern "C" void kernel_launch(void* const* d_in, const int* in_sizes, int n_in,
                              void* d_out, int out_size) {
    const float* q    = (const float*)d_in[0];
    const float* k    = (const float*)d_in[1];
    const float* v    = (const float*)d_in[2];
    const float* mask = (const float*)d_in[3];
    float* out = (float*)d_out;

    static bool attr_set = false;
    if (!attr_set) {
        cudaFuncSetAttribute(la_out_kernel,
                             cudaFuncAttributeMaxDynamicSharedMemorySize, P2_SMEM);
        attr_set = true;
    }

    la_kv_kernel<<<dim3(CH, Hh, Nb), 256>>>(k, v, mask);
    la_red_kernel<<<(KV4 + KS4 + 255) / 256, 256>>>();
    la_out_kernel<<<dim3(TS, Hh, Nb), 256, P2_SMEM>>>(q, out);
}

// round 13
// speedup vs baseline: 1.0451x; 1.0451x over previous
#include <cuda_runtime.h>
#include <cuda_bf16.h>
#include <cstdint>

// Fixed shapes
#define Nb 8
#define Ld 4096
#define Sd 4096
#define Hh 8
#define Dd 64
#define Mm 64
#define CH 16           // split-K chunks over S
#define SC (Sd / CH)    // 256 s-rows per chunk
#define TS 4            // phase-2 L segments: 256 CTAs
#define EPSV 1e-6f
#define NH (Nb * Hh)
#define KVF_NH 5120     // 8 k8 * 32 slots * 20 floats (permuted KV per head)

// Scratch (allocation-free rule: __device__ globals)
__device__ float g_KVp[CH * NH * Dd * Mm];   // per-chunk partial KV (fp32)
__device__ float g_Ksp[CH * NH * Dd];        // per-chunk partial Ksum (fp32)
__device__ float g_KVf[NH * KVF_NH];         // reduced KV, tf32 bits, fragment-permuted
__device__ float g_Ksum[NH * Dd];            // reduced Ksum (fp32)

__device__ __forceinline__ float phi(float x) {
    return x > 0.f ? x + 1.f : __expf(x);    // elu(x)+1
}

__device__ __forceinline__ uint32_t to_tf32(float x) {
    uint32_t u;
    asm("cvt.rna.tf32.f32 %0, %1;" : "=r"(u) : "f"(x));
    return u;
}

__device__ __forceinline__ void mma_tf32(float* d,
                                         uint32_t a0, uint32_t a1, uint32_t a2, uint32_t a3,
                                         uint32_t b0, uint32_t b1) {
    asm volatile(
        "mma.sync.aligned.m16n8k8.row.col.f32.tf32.tf32.f32 "
        "{%0,%1,%2,%3}, {%4,%5,%6,%7}, {%8,%9}, {%0,%1,%2,%3};\n"
        : "+f"(d[0]), "+f"(d[1]), "+f"(d[2]), "+f"(d[3])
        : "r"(a0), "r"(a1), "r"(a2), "r"(a3), "r"(b0), "r"(b1));
}

__device__ __forceinline__ void cp16(uint32_t saddr, const void* gaddr) {
    asm volatile("cp.async.cg.shared.global [%0], [%1], 16;\n"
                 :: "r"(saddr), "l"(gaddr));
}

// ───────────────────────── Phase 1: per-chunk KV partials ─────────────────────────
// grid (CH, H, N), 256 threads. K: LDG→phi·mask→tf32→STS (needs Ksum).
// V: cp.async.cg raw global→smem (double-buffered), cvt at fragment read.
__global__ __launch_bounds__(256) void la_kv_kernel(const float* __restrict__ kk,
                                                    const float* __restrict__ vv,
                                                    const float* __restrict__ mask) {
    const int c = blockIdx.x, h = blockIdx.y, n = blockIdx.z;
    const int nh = n * Hh + h;
    const int tid = threadIdx.x;
    const int warp = tid >> 5, lane = tid & 31;
    const int r = lane >> 2, q4 = lane & 3;
    const int d0 = (warp >> 1) * 16, m0 = (warp & 1) * 32;
    const int lrow = tid >> 4, lcol = tid & 15;

    __shared__ float Ks[32][72];        // tf32 bits of phi(K)*mask
    __shared__ float Vs[2][32][72];     // raw fp32 V (cp.async target)
    __shared__ float ksum_s[64];

    if (tid < 64) ksum_s[tid] = 0.f;

    float acc[4][4] = {};
    float ks4[4] = {0.f, 0.f, 0.f, 0.f};

    const size_t s0 = (size_t)c * SC;
    const float* kbase = kk + (size_t)n * Sd * 512 + h * Dd;
    const float* vbase = vv + (size_t)n * Sd * 512 + h * Mm;
    const float* mbase = mask + (size_t)n * Sd;

    const uint32_t vs_s = (uint32_t)__cvta_generic_to_shared(&Vs[0][0][0]);
    const int NTK = SC / 32;

    float4 kr[2];
    float mr[2];

    // prologue: V tile 0 via cp.async into buf 0; K tile 0 via LDG
    #pragma unroll
    for (int i = 0; i < 2; i++) {
        int chunk = tid + 256 * i;           // 0..511
        int row = chunk >> 4, cc = chunk & 15;
        cp16(vs_s + (row * 72 + cc * 4) * 4,
             vbase + (s0 + row) * 512 + cc * 4);
    }
    asm volatile("cp.async.commit_group;\n");
    #pragma unroll
    for (int p = 0; p < 2; p++) {
        size_t sg = s0 + p * 16 + lrow;
        kr[p] = *(const float4*)(kbase + sg * 512 + lcol * 4);
        mr[p] = __ldg(mbase + sg);
    }

    for (int it = 0; it < NTK; it++) {
        const int buf = it & 1;
        // transform K (consumes kr/mr)
        #pragma unroll
        for (int p = 0; p < 2; p++) {
            int row = p * 16 + lrow;
            float pk0 = phi(kr[p].x) * mr[p], pk1 = phi(kr[p].y) * mr[p];
            float pk2 = phi(kr[p].z) * mr[p], pk3 = phi(kr[p].w) * mr[p];
            ks4[0] += pk0; ks4[1] += pk1; ks4[2] += pk2; ks4[3] += pk3;
            uint4 ku; ku.x = to_tf32(pk0); ku.y = to_tf32(pk1);
                      ku.z = to_tf32(pk2); ku.w = to_tf32(pk3);
            *(uint4*)&Ks[row][lcol * 4] = ku;
        }

        // prefetch K it+1 (LDG) + issue V it+1 (cp.async into other buf)
        if (it + 1 < NTK) {
            #pragma unroll
            for (int p = 0; p < 2; p++) {
                size_t sg = s0 + (it + 1) * 32 + p * 16 + lrow;
                kr[p] = *(const float4*)(kbase + sg * 512 + lcol * 4);
                mr[p] = __ldg(mbase + sg);
            }
            uint32_t sbase = vs_s + (buf ^ 1) * 32 * 72 * 4;
            #pragma unroll
            for (int i = 0; i < 2; i++) {
                int chunk = tid + 256 * i;
                int row = chunk >> 4, cc = chunk & 15;
                cp16(sbase + (row * 72 + cc * 4) * 4,
                     vbase + (s0 + (it + 1) * 32 + row) * 512 + cc * 4);
            }
        }
        asm volatile("cp.async.commit_group;\n");
        asm volatile("cp.async.wait_group 1;\n" ::: "memory");   // V tile 'it' done
        __syncthreads();

        #pragma unroll
        for (int k8 = 0; k8 < 4; k8++) {
            int sA = k8 * 8 + q4;
            uint32_t a0 = __float_as_uint(Ks[sA][d0 + r]);
            uint32_t a1 = __float_as_uint(Ks[sA][d0 + r + 8]);
            uint32_t a2 = __float_as_uint(Ks[sA + 4][d0 + r]);
            uint32_t a3 = __float_as_uint(Ks[sA + 4][d0 + r + 8]);
            #pragma unroll
            for (int j = 0; j < 4; j++) {
                uint32_t b0 = to_tf32(Vs[buf][sA][m0 + 8 * j + r]);
                uint32_t b1 = to_tf32(Vs[buf][sA + 4][m0 + 8 * j + r]);
                mma_tf32(acc[j], a0, a1, a2, a3, b0, b1);
            }
        }
        __syncthreads();
    }

    #pragma unroll
    for (int q = 0; q < 4; q++) atomicAdd(&ksum_s[lcol * 4 + q], ks4[q]);
    __syncthreads();
    if (tid < 64) g_Ksp[(c * NH + nh) * Dd + tid] = ksum_s[tid];

    float* kvp = g_KVp + ((size_t)c * NH + nh) * (Dd * Mm);
    #pragma unroll
    for (int j = 0; j < 4; j++) {
        int m = m0 + 8 * j + 2 * q4;
        *(float2*)&kvp[(d0 + r) * Mm + m]     = make_float2(acc[j][0], acc[j][1]);
        *(float2*)&kvp[(d0 + r + 8) * Mm + m] = make_float2(acc[j][2], acc[j][3]);
    }
}

// ──── Reduce: CH partials → fragment-permuted tf32 KV (g_KVf) + Ksum ────
#define KV4 (NH * Dd * Mm / 4)     // 65536 float4
#define KS4 (NH * Dd / 4)          // 1024 float4
__global__ __launch_bounds__(256) void la_red_kernel() {
    int i = blockIdx.x * 256 + threadIdx.x;
    if (i < KV4) {
        float4 s = make_float4(0.f, 0.f, 0.f, 0.f);
        #pragma unroll
        for (int c = 0; c < CH; c++) {
            float4 x = *(const float4*)(g_KVp + (size_t)c * (NH * Dd * Mm) + i * 4);
            s.x += x.x; s.y += x.y; s.z += x.z; s.w += x.w;
        }
        int nhq = i >> 10;
        int inner = i & 1023;
        int d = inner >> 4;
        int mb = (inner & 15) * 4;
        int k8 = d >> 3, dq = d & 7;
        int q4 = dq & 3, bsel = dq >> 2;
        float* dst = g_KVf + (size_t)nhq * KVF_NH;
        float vals[4] = {s.x, s.y, s.z, s.w};
        #pragma unroll
        for (int t = 0; t < 4; t++) {
            int m = mb + t;
            int r = m & 7, j = m >> 3;
            dst[(k8 * 32 + r * 4 + q4) * 20 + bsel * 8 + j] =
                __uint_as_float(to_tf32(vals[t]));
        }
    } else if (i < KV4 + KS4) {
        int i2 = i - KV4;
        float4 s = make_float4(0.f, 0.f, 0.f, 0.f);
        #pragma unroll
        for (int c = 0; c < CH; c++) {
            float4 x = *(const float4*)(g_Ksp + c * (NH * Dd) + i2 * 4);
            s.x += x.x; s.y += x.y; s.z += x.z; s.w += x.w;
        }
        *(float4*)(g_Ksum + i2 * 4) = s;
    }
}

// ───────────── Phase 2: warp-autonomous, LDS.128 B fragments, Z via 9th mma tile ──
// (exact 77.9us champion — unchanged)
#define QROWP 68
#define SLOT  (16 * QROWP)
#define P2_SMEM ((KVF_NH + 8 * 2 * SLOT) * 4)

__global__ __launch_bounds__(256) void la_out_kernel(const float* __restrict__ qq,
                                                     float* __restrict__ out) {
    extern __shared__ float sm[];
    float* KVf = sm;
    float* Qring = sm + KVF_NH;

    const int seg = blockIdx.x, h = blockIdx.y, n = blockIdx.z;
    const int nh = n * Hh + h;
    const int tid = threadIdx.x;
    const int warp = tid >> 5, lane = tid & 31;
    const int r = lane >> 2, q4 = lane & 3;

    const float* kvb = g_KVf + (size_t)nh * KVF_NH;
    #pragma unroll
    for (int p = 0; p < 5; p++) {
        int idx4 = tid + p * 256;
        *(float4*)&KVf[idx4 * 4] = *(const float4*)(kvb + idx4 * 4);
    }

    const size_t lbase = (size_t)n * Ld + (size_t)seg * (Ld / TS);
    const float* qseg = qq + lbase * 512 + h * Dd;
    float* oseg = out + lbase * 512 + h * Mm;

    float* myring = Qring + warp * 2 * SLOT;
    const uint32_t ring_s = (uint32_t)__cvta_generic_to_shared(myring);

    const int NT = (Ld / TS) / (8 * 16);

    #pragma unroll
    for (int pre = 0; pre < 2; pre++) {
        int trow = (pre * 8 + warp) * 16;
        uint32_t sbase = ring_s + pre * SLOT * 4;
        #pragma unroll
        for (int i = 0; i < 8; i++) {
            int chunk = lane + 32 * i;
            int row = chunk >> 4, c = chunk & 15;
            cp16(sbase + (row * QROWP + c * 4) * 4,
                 qseg + (size_t)(trow + row) * 512 + c * 4);
        }
        asm volatile("cp.async.commit_group;\n");
    }

    __syncthreads();

    uint32_t ksAu[8], ksBu[8];
    const float* ksb = g_Ksum + nh * Dd;
    #pragma unroll
    for (int k8 = 0; k8 < 8; k8++) {
        ksAu[k8] = to_tf32(__ldg(ksb + 8 * k8 + q4));
        ksBu[k8] = to_tf32(__ldg(ksb + 8 * k8 + q4 + 4));
    }

    const int bslot = lane * 20;

    #pragma unroll 1
    for (int it = 0; it < NT; it++) {
        float* qs = myring + (it & 1) * SLOT;

        asm volatile("cp.async.wait_group 1;\n" ::: "memory");
        __syncwarp();

        float ar[8][4];
        #pragma unroll
        for (int k8 = 0; k8 < 8; k8++) {
            int dk = 8 * k8;
            ar[k8][0] = qs[r * QROWP + dk + q4];
            ar[k8][1] = qs[(r + 8) * QROWP + dk + q4];
            ar[k8][2] = qs[r * QROWP + dk + q4 + 4];
            ar[k8][3] = qs[(r + 8) * QROWP + dk + q4 + 4];
        }
        __syncwarp();

        if (it + 2 < NT) {
            int trow = ((it + 2) * 8 + warp) * 16;
            uint32_t sbase = ring_s + (it & 1) * SLOT * 4;
            #pragma unroll
            for (int i = 0; i < 8; i++) {
                int chunk = lane + 32 * i;
                int row = chunk >> 4, c = chunk & 15;
                cp16(sbase + (row * QROWP + c * 4) * 4,
                     qseg + (size_t)(trow + row) * 512 + c * 4);
            }
        }
        asm volatile("cp.async.commit_group;\n");

        uint32_t af[8][4];
        #pragma unroll
        for (int k8 = 0; k8 < 8; k8++) {
            af[k8][0] = to_tf32(phi(ar[k8][0]));
            af[k8][1] = to_tf32(phi(ar[k8][1]));
            af[k8][2] = to_tf32(phi(ar[k8][2]));
            af[k8][3] = to_tf32(phi(ar[k8][3]));
        }

        float acc[8][4] = {};
        float accz[4] = {};
        #pragma unroll
        for (int k8 = 0; k8 < 8; k8++) {
            const float* bp = &KVf[k8 * 640 + bslot];
            float4 b01 = *(const float4*)(bp);
            float4 b02 = *(const float4*)(bp + 4);
            float4 b11 = *(const float4*)(bp + 8);
            float4 b12 = *(const float4*)(bp + 12);
            const float b0a[8] = {b01.x, b01.y, b01.z, b01.w, b02.x, b02.y, b02.z, b02.w};
            const float b1a[8] = {b11.x, b11.y, b11.z, b11.w, b12.x, b12.y, b12.z, b12.w};
            #pragma unroll
            for (int j = 0; j < 8; j++)
                mma_tf32(acc[j], af[k8][0], af[k8][1], af[k8][2], af[k8][3],
                         __float_as_uint(b0a[j]), __float_as_uint(b1a[j]));
            mma_tf32(accz, af[k8][0], af[k8][1], af[k8][2], af[k8][3],
                     ksAu[k8], ksBu[k8]);
        }
        float z1 = 1.f / (accz[0] + EPSV);
        float z2 = 1.f / (accz[2] + EPSV);

        int trow = (it * 8 + warp) * 16;
        float* ob = oseg + (size_t)trow * 512;
        #pragma unroll
        for (int j = 0; j < 8; j++) {
            int m = 8 * j + 2 * q4;
            *(float2*)&ob[(size_t)r * 512 + m] =
                make_float2(acc[j][0] * z1, acc[j][1] * z1);
            *(float2*)&ob[(size_t)(r + 8) * 512 + m] =
                make_float2(acc[j][2] * z2, acc[j][3] * z2);
        }
    }
}

extern "C" void kernel_launch(void* const* d_in, const int* in_sizes, int n_in,
                              void* d_out, int out_size) {
    const float* q    = (const float*)d_in[0];
    const float* k    = (const float*)d_in[1];
    const float* v    = (const float*)d_in[2];
    const float* mask = (const float*)d_in[3];
    float* out = (float*)d_out;

    static bool attr_set = false;
    if (!attr_set) {
        cudaFuncSetAttribute(la_out_kernel,
                             cudaFuncAttributeMaxDynamicSharedMemorySize, P2_SMEM);
        attr_set = true;
    }

    la_kv_kernel<<<dim3(CH, Hh, Nb), 256>>>(k, v, mask);
    la_red_kernel<<<(KV4 + KS4 + 255) / 256, 256>>>();
    la_out_kernel<<<dim3(TS, Hh, Nb), 256, P2_SMEM>>>(q, out);
}